// round 15
// baseline (speedup 1.0000x reference)
#include <cuda_runtime.h>
#include <cuda_fp16.h>
#include <math.h>
#include <stdint.h>

#define BB   2
#define TT   2048
#define DD   2048
#define NH   16
#define NKV  4
#define HDQ  128
#define BT   4096   // BB*TT
#define KDIM 2048
#define NQKV 3072   // fused Q(2048)+K(512)+V(512) output width
#define QSCALE 0.08838834764831845f

// ---------------- scratch (static device globals: no allocs allowed) --------
__device__ __half g_xh[(size_t)BT * KDIM];        // x fp16 [M][K]
__device__ __half g_ah[(size_t)BT * KDIM];        // attn-out fp16 [M][K]
__device__ __half g_wqkvt[(size_t)NQKV * KDIM];   // fused [N][K] fp16 weights
__device__ __half g_wot[(size_t)2048 * KDIM];
__device__ float g_rcos[TT * 64];
__device__ float g_rsin[TT * 64];

// attention operands fp16
__device__ __half g_Qf[(size_t)BT * 2048];
__device__ __half g_Kf[(size_t)BT * 512];
__device__ __half g_Vf[(size_t)BT * 512];

// ---------------- helpers ----------------------------------------------------
__device__ __forceinline__ uint32_t smem_u32(const void* p) {
    uint32_t a;
    asm("{ .reg .u64 t; cvta.to.shared.u64 t, %1; cvt.u32.u64 %0, t; }"
        : "=r"(a) : "l"(p));
    return a;
}
__device__ __forceinline__ void ldm_x4(uint32_t& r0, uint32_t& r1,
                                       uint32_t& r2, uint32_t& r3, uint32_t addr) {
    asm volatile("ldmatrix.sync.aligned.m8n8.x4.shared.b16 {%0,%1,%2,%3}, [%4];"
                 : "=r"(r0), "=r"(r1), "=r"(r2), "=r"(r3) : "r"(addr));
}
__device__ __forceinline__ void ldm_x4t(uint32_t& r0, uint32_t& r1,
                                        uint32_t& r2, uint32_t& r3, uint32_t addr) {
    asm volatile("ldmatrix.sync.aligned.m8n8.x4.trans.shared.b16 {%0,%1,%2,%3}, [%4];"
                 : "=r"(r0), "=r"(r1), "=r"(r2), "=r"(r3) : "r"(addr));
}
__device__ __forceinline__ void mma16816(float* d, const uint32_t* a, const uint32_t* b) {
    asm volatile("mma.sync.aligned.m16n8k16.row.col.f32.f16.f16.f32 "
                 "{%0,%1,%2,%3}, {%4,%5,%6,%7}, {%8,%9}, {%0,%1,%2,%3};"
                 : "+f"(d[0]), "+f"(d[1]), "+f"(d[2]), "+f"(d[3])
                 : "r"(a[0]), "r"(a[1]), "r"(a[2]), "r"(a[3]),
                   "r"(b[0]), "r"(b[1]));
}
__device__ __forceinline__ void cp_async16(uint32_t saddr, const void* gaddr) {
    asm volatile("cp.async.cg.shared.global [%0], [%1], 16;"
                 :: "r"(saddr), "l"(gaddr) : "memory");
}
#define CP_COMMIT() asm volatile("cp.async.commit_group;" ::: "memory")
#define CP_WAIT1()  asm volatile("cp.async.wait_group 1;" ::: "memory")
#define CP_WAIT0()  asm volatile("cp.async.wait_group 0;" ::: "memory")

__device__ __forceinline__ uint32_t pack_h2(float a, float b) {
    __half2 t = __floats2half2_rn(a, b);
    return *reinterpret_cast<uint32_t*>(&t);
}

// ---------------- fused conversion kernel ------------------------------------
// One launch handling: wq/wk/wv/wo transpose+convert, x convert, rope table.
// Block ranges (256 threads each):
//   [0,4096)      wq  tconv  (N=2048)
//   [4096,5120)   wk  tconv  (N=512)  -> wqkvt + 2048*KDIM
//   [5120,6144)   wv  tconv  (N=512)  -> wqkvt + 2560*KDIM
//   [6144,10240)  wo  tconv  (N=2048) -> wot
//   [10240,18432) x   conv4  (2M float4)
//   [18432,18944) rope table (131072 items)
__device__ __forceinline__ void tconv_block(const float* __restrict__ W,
                                            __half* __restrict__ Wt,
                                            int N, int bx, int by, int tid)
{
    __shared__ float tile[32][33];
    int tx = tid & 31, ty = tid >> 5;
    int nb = bx * 32, kb = by * 32;
    #pragma unroll
    for (int r = 0; r < 4; ++r)
        tile[ty + r * 8][tx] = W[(size_t)(kb + ty + r * 8) * N + nb + tx];
    __syncthreads();
    #pragma unroll
    for (int r = 0; r < 4; ++r) {
        int n = nb + ty + r * 8;
        Wt[(size_t)n * KDIM + kb + tx] = __float2half(tile[tx][ty + r * 8]);
    }
}

__global__ __launch_bounds__(256) void megaconv_kernel(
    const float* __restrict__ x,  const float* __restrict__ wq,
    const float* __restrict__ wk, const float* __restrict__ wv,
    const float* __restrict__ wo,
    __half* __restrict__ xh, __half* __restrict__ wqkvt, __half* __restrict__ wot)
{
    const int bid = blockIdx.x;
    const int tid = threadIdx.x;
    if (bid < 4096) {
        tconv_block(wq, wqkvt, 2048, bid & 63, bid >> 6, tid);
    } else if (bid < 5120) {
        int r = bid - 4096;
        tconv_block(wk, wqkvt + (size_t)2048 * KDIM, 512, r & 15, r >> 4, tid);
    } else if (bid < 6144) {
        int r = bid - 5120;
        tconv_block(wv, wqkvt + (size_t)2560 * KDIM, 512, r & 15, r >> 4, tid);
    } else if (bid < 10240) {
        int r = bid - 6144;
        tconv_block(wo, wot, 2048, r & 63, r >> 6, tid);
    } else if (bid < 18432) {
        int i = (bid - 10240) * 256 + tid;     // < 2097152 exactly
        float4 v = ((const float4*)x)[i];
        __half2 a = __floats2half2_rn(v.x, v.y);
        __half2 b = __floats2half2_rn(v.z, v.w);
        uint2 o = make_uint2(*reinterpret_cast<uint32_t*>(&a),
                             *reinterpret_cast<uint32_t*>(&b));
        ((uint2*)xh)[i] = o;
    } else {
        int i = (bid - 18432) * 256 + tid;     // < 131072 exactly
        int t = i >> 6, d = i & 63;
        double inv = exp2(-(double)d * (19.931568569324174 / 64.0));
        double ang = (double)t * inv;
        g_rcos[i] = (float)cos(ang);
        g_rsin[i] = (float)sin(ang);
    }
}
#define MEGACONV_BLOCKS 18944

// ---------------- shared GEMM mainloop: K-chunk 64, 3-stage cp.async ---------
#define GST       72                            // smem row stride (halves)
#define GSTAGE_H  (128 * GST)                   // halves per matrix per stage
#define G_PIPE_B  (6 * GSTAGE_H * 2)            // 110592 bytes
#define G_EPI_B   (128 * 132 * 4)               // 67584 bytes (fp32 C tile)
#define G_SMEM_B  (G_PIPE_B)                    // max(pipe, epi)

__device__ __forceinline__ void gemm_mainloop(
    const __half* __restrict__ A, const __half* __restrict__ Bt,
    int mBase, int nBase, int K, uint32_t smb,
    int tid, int lane, int wm, int wn, float acc[2][8][4])
{
    const int NC = K >> 6;                      // 64-wide chunks
    const int lrow = tid >> 1;                  // 0..127
    const int lseg = (tid & 1) << 5;            // 0 or 32 halves
    const int ldRow = lane & 15;
    const int ldCol = (lane >> 4) << 3;

    const __half* gA = A  + (size_t)(mBase + lrow) * K + lseg;
    const __half* gB = Bt + (size_t)(nBase + lrow) * K + lseg;
    const uint32_t sOff = (uint32_t)(lrow * GST + lseg) * 2;

    auto issue = [&](int c, int s) {
        const __half* ga = gA + c * 64;
        const __half* gb = gB + c * 64;
        uint32_t sa = smb + (uint32_t)s * (GSTAGE_H * 2) + sOff;
        uint32_t sb = smb + (uint32_t)(3 * GSTAGE_H * 2) + (uint32_t)s * (GSTAGE_H * 2) + sOff;
        cp_async16(sa,      ga);
        cp_async16(sa + 16, ga + 8);
        cp_async16(sa + 32, ga + 16);
        cp_async16(sa + 48, ga + 24);
        cp_async16(sb,      gb);
        cp_async16(sb + 16, gb + 8);
        cp_async16(sb + 32, gb + 16);
        cp_async16(sb + 48, gb + 24);
        CP_COMMIT();
    };

    issue(0, 0);
    issue(1, 1);

    int stage = 0;
    for (int c = 0; c < NC; ++c) {
        if (c + 1 < NC) CP_WAIT1(); else CP_WAIT0();
        __syncthreads();
        if (c + 2 < NC) {
            int ns = stage + 2; if (ns >= 3) ns -= 3;
            issue(c + 2, ns);
        }
        const uint32_t sA = smb + (uint32_t)stage * (GSTAGE_H * 2);
        const uint32_t sB = smb + (uint32_t)(3 * GSTAGE_H * 2) + (uint32_t)stage * (GSTAGE_H * 2);
        #pragma unroll
        for (int ks = 0; ks < 4; ++ks) {
            uint32_t af[2][4], bfr[8][2];
            #pragma unroll
            for (int mf = 0; mf < 2; ++mf) {
                uint32_t addr = sA + ((wm * 32 + mf * 16 + ldRow) * GST
                                      + ks * 16 + ldCol) * 2;
                ldm_x4(af[mf][0], af[mf][1], af[mf][2], af[mf][3], addr);
            }
            #pragma unroll
            for (int ng = 0; ng < 4; ++ng) {
                uint32_t r0, r1, r2, r3;
                uint32_t addr = sB + ((wn * 64 + ng * 16 + ldRow) * GST
                                      + ks * 16 + ldCol) * 2;
                ldm_x4(r0, r1, r2, r3, addr);
                bfr[ng * 2 + 0][0] = r0; bfr[ng * 2 + 1][0] = r1;
                bfr[ng * 2 + 0][1] = r2; bfr[ng * 2 + 1][1] = r3;
            }
            #pragma unroll
            for (int mf = 0; mf < 2; ++mf)
                #pragma unroll
                for (int nf = 0; nf < 8; ++nf)
                    mma16816(acc[mf][nf], af[mf], bfr[nf]);
        }
        ++stage; if (stage == 3) stage = 0;
    }
}

// ---------------- GEMM with plain fp32 epilogue (output projection) ----------
__global__ __launch_bounds__(256, 2) void gemm_kernel(
    const __half* __restrict__ A, const __half* __restrict__ Bt,
    float* __restrict__ C, int N, int K)
{
    extern __shared__ __half gsm[];
    const uint32_t smb = smem_u32(gsm);
    const int tid = threadIdx.x;
    const int lane = tid & 31, wid = tid >> 5;
    const int wm = wid & 3, wn = wid >> 2;
    const int mBase = blockIdx.y << 7, nBase = blockIdx.x << 7;

    float acc[2][8][4];
    #pragma unroll
    for (int i = 0; i < 2; ++i)
        #pragma unroll
        for (int j = 0; j < 8; ++j)
            #pragma unroll
            for (int r = 0; r < 4; ++r) acc[i][j][r] = 0.f;

    gemm_mainloop(A, Bt, mBase, nBase, K, smb, tid, lane, wm, wn, acc);

    const int gid = lane >> 2, tig = lane & 3;
    #pragma unroll
    for (int mf = 0; mf < 2; ++mf) {
        #pragma unroll
        for (int nf = 0; nf < 8; ++nf) {
            int row = mBase + wm * 32 + mf * 16 + gid;
            int col = nBase + wn * 64 + nf * 8 + tig * 2;
            float2 v0 = make_float2(acc[mf][nf][0], acc[mf][nf][1]);
            float2 v1 = make_float2(acc[mf][nf][2], acc[mf][nf][3]);
            *(float2*)&C[(size_t)row * N + col] = v0;
            *(float2*)&C[(size_t)(row + 8) * N + col] = v1;
        }
    }
}

// ---------------- fused QKV GEMM: rope + fp16 convert in epilogue ------------
__global__ __launch_bounds__(256, 2) void gemm_qkv_kernel(
    const __half* __restrict__ A, const __half* __restrict__ Bt,
    __half* __restrict__ qf, __half* __restrict__ kf, __half* __restrict__ vf,
    int K)
{
    extern __shared__ __half gsm[];
    const uint32_t smb = smem_u32(gsm);
    const int tid = threadIdx.x;
    const int lane = tid & 31, wid = tid >> 5;
    const int wm = wid & 3, wn = wid >> 2;
    const int mBase = blockIdx.y << 7, nBase = blockIdx.x << 7;

    float acc[2][8][4];
    #pragma unroll
    for (int i = 0; i < 2; ++i)
        #pragma unroll
        for (int j = 0; j < 8; ++j)
            #pragma unroll
            for (int r = 0; r < 4; ++r) acc[i][j][r] = 0.f;

    gemm_mainloop(A, Bt, mBase, nBase, K, smb, tid, lane, wm, wn, acc);

    // stage fp32 C tile in smem (reuse pipeline buffers)
    float* Cs = (float*)gsm;
    __syncthreads();
    const int gid = lane >> 2, tig = lane & 3;
    #pragma unroll
    for (int mf = 0; mf < 2; ++mf) {
        #pragma unroll
        for (int nf = 0; nf < 8; ++nf) {
            int r = wm * 32 + mf * 16 + gid;
            int col = wn * 64 + nf * 8 + tig * 2;
            *(float2*)&Cs[r * 132 + col] = make_float2(acc[mf][nf][0], acc[mf][nf][1]);
            *(float2*)&Cs[(r + 8) * 132 + col] = make_float2(acc[mf][nf][2], acc[mf][nf][3]);
        }
    }
    __syncthreads();

    if (nBase < 2048) {                    // Q head: rope + scale
        for (int p = tid; p < 128 * 64; p += 256) {
            int r = p >> 6, d = p & 63;
            int row = mBase + r;
            int t = row & (TT - 1);
            float c = g_rcos[t * 64 + d], s = g_rsin[t * 64 + d];
            float u1 = Cs[r * 132 + d], u2 = Cs[r * 132 + d + 64];
            __half* op = qf + (size_t)row * 2048 + nBase;
            op[d]      = __float2half((u1 * c - u2 * s) * QSCALE);
            op[d + 64] = __float2half((u2 * c + u1 * s) * QSCALE);
        }
    } else if (nBase < 2560) {             // K head: rope
        int colb = nBase - 2048;
        for (int p = tid; p < 128 * 64; p += 256) {
            int r = p >> 6, d = p & 63;
            int row = mBase + r;
            int t = row & (TT - 1);
            float c = g_rcos[t * 64 + d], s = g_rsin[t * 64 + d];
            float u1 = Cs[r * 132 + d], u2 = Cs[r * 132 + d + 64];
            __half* op = kf + (size_t)row * 512 + colb;
            op[d]      = __float2half(u1 * c - u2 * s);
            op[d + 64] = __float2half(u2 * c + u1 * s);
        }
    } else {                               // V: plain convert
        int colb = nBase - 2560;
        for (int p = tid; p < 128 * 128; p += 256) {
            int r = p >> 7, d = p & 127;
            int row = mBase + r;
            vf[(size_t)row * 512 + colb + d] = __float2half(Cs[r * 132 + d]);
        }
    }
}

// ---------------- fp16 tensor-core flash attention (2-stage K/V pipeline) ----
#define AST 136
#define ATT_SMEM (5 * 64 * AST * 2)   // Q + 2 x (K,V) stages = 87040 B

__global__ __launch_bounds__(128) void attn_mma_kernel(
    const __half* __restrict__ Qf, const __half* __restrict__ Kf,
    const __half* __restrict__ Vf, __half* __restrict__ Oo)
{
    extern __shared__ __half smh[];
    __half* sQ = smh;
    __half* sKV = sQ + 64 * AST;

    const int tid = threadIdx.x;
    const int lane = tid & 31, wm = tid >> 5;
    const int gid = lane >> 2, tig = lane & 3;
    const int ldRow = lane & 15, ldCol = (lane >> 4) << 3;
    const int qt = gridDim.x - 1 - blockIdx.x;
    const int h = blockIdx.y, b = blockIdx.z;
    const int hk = h >> 2;
    const int qBase = qt * 64;

    const uint32_t aQ = smem_u32(sQ);
    const uint32_t aKV = smem_u32(sKV);
    const uint32_t stageB = 2 * 64 * AST * 2;
    const uint32_t vOffB  = 64 * AST * 2;

    auto issue = [&](int kt, int s) {
        const size_t base = ((size_t)(b * TT + kt * 64)) * 512 + hk * 128;
        uint32_t sk = aKV + (uint32_t)s * stageB;
        #pragma unroll
        for (int j = 0; j < 8; ++j) {
            int idx = j * 128 + tid;
            int r = idx >> 4, c = (idx & 15) << 3;
            size_t g = base + (size_t)r * 512 + c;
            uint32_t so = (uint32_t)(r * AST + c) * 2;
            cp_async16(sk + so, Kf + g);
            cp_async16(sk + vOffB + so, Vf + g);
        }
        CP_COMMIT();
    };

    issue(0, 0);

    {
        const __half* gq = Qf + ((size_t)(b * TT + qBase)) * 2048 + h * 128;
        for (int idx = tid; idx < 1024; idx += 128) {
            int r = idx >> 4, c = (idx & 15) << 3;
            *(uint4*)&sQ[r * AST + c] = *(const uint4*)(gq + (size_t)r * 2048 + c);
        }
    }

    float oacc[16][4];
    #pragma unroll
    for (int i = 0; i < 16; ++i)
        #pragma unroll
        for (int r = 0; r < 4; ++r) oacc[i][r] = 0.f;
    float mrow[2] = {-INFINITY, -INFINITY};
    float lrow[2] = {0.f, 0.f};

    for (int kt = 0; kt <= qt; ++kt) {
        __syncthreads();
        if (kt + 1 <= qt) { issue(kt + 1, (kt + 1) & 1); CP_WAIT1(); }
        else              { CP_WAIT0(); }
        __syncthreads();

        const uint32_t aK = aKV + (uint32_t)(kt & 1) * stageB;
        const uint32_t aV = aK + vOffB;

        float sacc[8][4];
        #pragma unroll
        for (int i = 0; i < 8; ++i)
            #pragma unroll
            for (int r = 0; r < 4; ++r) sacc[i][r] = 0.f;

        #pragma unroll
        for (int ks = 0; ks < 8; ++ks) {
            uint32_t aq[4];
            uint32_t qoff = ((wm * 16 + ldRow) * AST + ks * 16 + ldCol) * 2;
            ldm_x4(aq[0], aq[1], aq[2], aq[3], aQ + qoff);
            #pragma unroll
            for (int j = 0; j < 4; ++j) {
                uint32_t koff = ((j * 16 + ldRow) * AST + ks * 16 + ldCol) * 2;
                uint32_t r0, r1, r2, r3;
                ldm_x4(r0, r1, r2, r3, aK + koff);
                uint32_t b0[2] = {r0, r2}, b1[2] = {r1, r3};
                mma16816(sacc[2 * j], aq, b0);
                mma16816(sacc[2 * j + 1], aq, b1);
            }
        }

        if (kt == qt) {
            int lr0 = wm * 16 + gid, lr1 = lr0 + 8;
            #pragma unroll
            for (int nb = 0; nb < 8; ++nb) {
                int lc = nb * 8 + tig * 2;
                if (lc > lr0)     sacc[nb][0] = -1e30f;
                if (lc + 1 > lr0) sacc[nb][1] = -1e30f;
                if (lc > lr1)     sacc[nb][2] = -1e30f;
                if (lc + 1 > lr1) sacc[nb][3] = -1e30f;
            }
        }

        #pragma unroll
        for (int hf = 0; hf < 2; ++hf) {
            float rmax = -1e30f;
            #pragma unroll
            for (int nb = 0; nb < 8; ++nb)
                rmax = fmaxf(rmax, fmaxf(sacc[nb][hf * 2], sacc[nb][hf * 2 + 1]));
            rmax = fmaxf(rmax, __shfl_xor_sync(0xffffffffu, rmax, 1));
            rmax = fmaxf(rmax, __shfl_xor_sync(0xffffffffu, rmax, 2));
            float mnew = fmaxf(mrow[hf], rmax);
            float f = __expf(mrow[hf] - mnew);
            mrow[hf] = mnew;
            float rsum = 0.f;
            #pragma unroll
            for (int nb = 0; nb < 8; ++nb) {
                float s0 = __expf(sacc[nb][hf * 2] - mnew);
                float s1 = __expf(sacc[nb][hf * 2 + 1] - mnew);
                sacc[nb][hf * 2] = s0;
                sacc[nb][hf * 2 + 1] = s1;
                rsum += s0 + s1;
            }
            rsum += __shfl_xor_sync(0xffffffffu, rsum, 1);
            rsum += __shfl_xor_sync(0xffffffffu, rsum, 2);
            lrow[hf] = lrow[hf] * f + rsum;
            #pragma unroll
            for (int nb = 0; nb < 16; ++nb) {
                oacc[nb][hf * 2] *= f;
                oacc[nb][hf * 2 + 1] *= f;
            }
        }

        uint32_t ph[4][4];
        #pragma unroll
        for (int ks = 0; ks < 4; ++ks) {
            ph[ks][0] = pack_h2(sacc[2 * ks][0], sacc[2 * ks][1]);
            ph[ks][1] = pack_h2(sacc[2 * ks][2], sacc[2 * ks][3]);
            ph[ks][2] = pack_h2(sacc[2 * ks + 1][0], sacc[2 * ks + 1][1]);
            ph[ks][3] = pack_h2(sacc[2 * ks + 1][2], sacc[2 * ks + 1][3]);
        }

        #pragma unroll
        for (int ks = 0; ks < 4; ++ks) {
            #pragma unroll
            for (int j = 0; j < 8; ++j) {
                uint32_t voff = ((ks * 16 + ldRow) * AST + j * 16 + ldCol) * 2;
                uint32_t r0, r1, r2, r3;
                ldm_x4t(r0, r1, r2, r3, aV + voff);
                uint32_t v0[2] = {r0, r1}, v1[2] = {r2, r3};
                mma16816(oacc[2 * j], ph[ks], v0);
                mma16816(oacc[2 * j + 1], ph[ks], v1);
            }
        }
    }

    float inv0 = 1.f / lrow[0], inv1 = 1.f / lrow[1];
    size_t row0 = (size_t)(b * TT + qBase + wm * 16 + gid);
    __half* p0 = Oo + row0 * KDIM + h * 128 + tig * 2;
    __half* p1 = Oo + (row0 + 8) * KDIM + h * 128 + tig * 2;
    #pragma unroll
    for (int nb = 0; nb < 16; ++nb) {
        *(uint32_t*)(p0 + nb * 8) = pack_h2(oacc[nb][0] * inv0, oacc[nb][1] * inv0);
        *(uint32_t*)(p1 + nb * 8) = pack_h2(oacc[nb][2] * inv1, oacc[nb][3] * inv1);
    }
}

// ---------------- launcher ---------------------------------------------------
extern "C" void kernel_launch(void* const* d_in, const int* in_sizes, int n_in,
                              void* d_out, int out_size)
{
    const float* x  = (const float*)d_in[0];
    const float* wq = (const float*)d_in[1];
    const float* wk = (const float*)d_in[2];
    const float* wv = (const float*)d_in[3];
    const float* wo = (const float*)d_in[4];
    float* out = (float*)d_out;

    __half *xh, *ah, *wqkvt, *wot, *qf, *kf, *vf;
    cudaGetSymbolAddress((void**)&xh, g_xh);
    cudaGetSymbolAddress((void**)&ah, g_ah);
    cudaGetSymbolAddress((void**)&wqkvt, g_wqkvt);
    cudaGetSymbolAddress((void**)&wot, g_wot);
    cudaGetSymbolAddress((void**)&qf, g_Qf);
    cudaGetSymbolAddress((void**)&kf, g_Kf);
    cudaGetSymbolAddress((void**)&vf, g_Vf);

    cudaFuncSetAttribute(attn_mma_kernel,
                         cudaFuncAttributeMaxDynamicSharedMemorySize, ATT_SMEM);
    cudaFuncSetAttribute(gemm_kernel,
                         cudaFuncAttributeMaxDynamicSharedMemorySize, G_SMEM_B);
    cudaFuncSetAttribute(gemm_qkv_kernel,
                         cudaFuncAttributeMaxDynamicSharedMemorySize, G_SMEM_B);

    // all conversions + rope table in ONE launch
    megaconv_kernel<<<MEGACONV_BLOCKS, 256>>>(x, wq, wk, wv, wo, xh, wqkvt, wot);

    // fused QKV projection + rope + fp16 convert (one GEMM, N=3072)
    gemm_qkv_kernel<<<dim3(NQKV / 128, BT / 128), 256, G_SMEM_B>>>(xh, wqkvt,
                                                                   qf, kf, vf, KDIM);

    // fp16 tensor-core flash attention -> ah
    attn_mma_kernel<<<dim3(TT / 64, NH, BB), 128, ATT_SMEM>>>(qf, kf, vf, ah);

    // Output projection (fp32 out)
    gemm_kernel<<<dim3(2048 / 128, BT / 128), 256, G_SMEM_B>>>(ah, wot, out, 2048, KDIM);
}

// round 16
// speedup vs baseline: 1.0517x; 1.0517x over previous
#include <cuda_runtime.h>
#include <cuda_fp16.h>
#include <math.h>
#include <stdint.h>

#define BB   2
#define TT   2048
#define DD   2048
#define NH   16
#define NKV  4
#define HDQ  128
#define BT   4096   // BB*TT
#define KDIM 2048
#define NQKV 3072   // fused Q(2048)+K(512)+V(512) output width
#define QSCALE 0.08838834764831845f

// ---------------- scratch (static device globals: no allocs allowed) --------
__device__ __half g_xh[(size_t)BT * KDIM];        // x fp16 [M][K]
__device__ __half g_ah[(size_t)BT * KDIM];        // attn-out fp16 [M][K]
__device__ __half g_wqkvt[(size_t)NQKV * KDIM];   // fused [N][K] fp16 weights
__device__ __half g_wot[(size_t)2048 * KDIM];
__device__ float g_rcos[TT * 64];
__device__ float g_rsin[TT * 64];

// attention operands fp16
__device__ __half g_Qf[(size_t)BT * 2048];
__device__ __half g_Kf[(size_t)BT * 512];
__device__ __half g_Vf[(size_t)BT * 512];

// ---------------- helpers ----------------------------------------------------
__device__ __forceinline__ uint32_t smem_u32(const void* p) {
    uint32_t a;
    asm("{ .reg .u64 t; cvta.to.shared.u64 t, %1; cvt.u32.u64 %0, t; }"
        : "=r"(a) : "l"(p));
    return a;
}
__device__ __forceinline__ void ldm_x4(uint32_t& r0, uint32_t& r1,
                                       uint32_t& r2, uint32_t& r3, uint32_t addr) {
    asm volatile("ldmatrix.sync.aligned.m8n8.x4.shared.b16 {%0,%1,%2,%3}, [%4];"
                 : "=r"(r0), "=r"(r1), "=r"(r2), "=r"(r3) : "r"(addr));
}
__device__ __forceinline__ void ldm_x4t(uint32_t& r0, uint32_t& r1,
                                        uint32_t& r2, uint32_t& r3, uint32_t addr) {
    asm volatile("ldmatrix.sync.aligned.m8n8.x4.trans.shared.b16 {%0,%1,%2,%3}, [%4];"
                 : "=r"(r0), "=r"(r1), "=r"(r2), "=r"(r3) : "r"(addr));
}
__device__ __forceinline__ void mma16816(float* d, const uint32_t* a, const uint32_t* b) {
    asm volatile("mma.sync.aligned.m16n8k16.row.col.f32.f16.f16.f32 "
                 "{%0,%1,%2,%3}, {%4,%5,%6,%7}, {%8,%9}, {%0,%1,%2,%3};"
                 : "+f"(d[0]), "+f"(d[1]), "+f"(d[2]), "+f"(d[3])
                 : "r"(a[0]), "r"(a[1]), "r"(a[2]), "r"(a[3]),
                   "r"(b[0]), "r"(b[1]));
}
__device__ __forceinline__ void cp_async16(uint32_t saddr, const void* gaddr) {
    asm volatile("cp.async.cg.shared.global [%0], [%1], 16;"
                 :: "r"(saddr), "l"(gaddr) : "memory");
}
#define CP_COMMIT() asm volatile("cp.async.commit_group;" ::: "memory")
#define CP_WAIT2()  asm volatile("cp.async.wait_group 2;" ::: "memory")
#define CP_WAIT1()  asm volatile("cp.async.wait_group 1;" ::: "memory")
#define CP_WAIT0()  asm volatile("cp.async.wait_group 0;" ::: "memory")

__device__ __forceinline__ uint32_t pack_h2(float a, float b) {
    __half2 t = __floats2half2_rn(a, b);
    return *reinterpret_cast<uint32_t*>(&t);
}

// ---------------- fused conversion kernel ------------------------------------
// One launch: wq/wk/wv/wo transpose+convert, x convert, rope table.
__device__ __forceinline__ void tconv_block(const float* __restrict__ W,
                                            __half* __restrict__ Wt,
                                            int N, int bx, int by, int tid)
{
    __shared__ float tile[32][33];
    int tx = tid & 31, ty = tid >> 5;
    int nb = bx * 32, kb = by * 32;
    #pragma unroll
    for (int r = 0; r < 4; ++r)
        tile[ty + r * 8][tx] = W[(size_t)(kb + ty + r * 8) * N + nb + tx];
    __syncthreads();
    #pragma unroll
    for (int r = 0; r < 4; ++r) {
        int n = nb + ty + r * 8;
        Wt[(size_t)n * KDIM + kb + tx] = __float2half(tile[tx][ty + r * 8]);
    }
}

__global__ __launch_bounds__(256) void megaconv_kernel(
    const float* __restrict__ x,  const float* __restrict__ wq,
    const float* __restrict__ wk, const float* __restrict__ wv,
    const float* __restrict__ wo,
    __half* __restrict__ xh, __half* __restrict__ wqkvt, __half* __restrict__ wot)
{
    const int bid = blockIdx.x;
    const int tid = threadIdx.x;
    if (bid < 4096) {
        tconv_block(wq, wqkvt, 2048, bid & 63, bid >> 6, tid);
    } else if (bid < 5120) {
        int r = bid - 4096;
        tconv_block(wk, wqkvt + (size_t)2048 * KDIM, 512, r & 15, r >> 4, tid);
    } else if (bid < 6144) {
        int r = bid - 5120;
        tconv_block(wv, wqkvt + (size_t)2560 * KDIM, 512, r & 15, r >> 4, tid);
    } else if (bid < 10240) {
        int r = bid - 6144;
        tconv_block(wo, wot, 2048, r & 63, r >> 6, tid);
    } else if (bid < 18432) {
        int i = (bid - 10240) * 256 + tid;     // < 2097152 exactly
        float4 v = ((const float4*)x)[i];
        __half2 a = __floats2half2_rn(v.x, v.y);
        __half2 b = __floats2half2_rn(v.z, v.w);
        uint2 o = make_uint2(*reinterpret_cast<uint32_t*>(&a),
                             *reinterpret_cast<uint32_t*>(&b));
        ((uint2*)xh)[i] = o;
    } else {
        int i = (bid - 18432) * 256 + tid;     // < 131072 exactly
        int t = i >> 6, d = i & 63;
        double inv = exp2(-(double)d * (19.931568569324174 / 64.0));
        double ang = (double)t * inv;
        g_rcos[i] = (float)cos(ang);
        g_rsin[i] = (float)sin(ang);
    }
}
#define MEGACONV_BLOCKS 18944

// ---------------- GEMM mainloop: K-chunk 32, 4-stage cp.async ----------------
#define GST       40                            // smem row stride (halves)
#define GSTAGE_H  (128 * GST)                   // 5120 halves per matrix/stage
#define G_PIPE_B  (8 * GSTAGE_H * 2)            // 81920 bytes (4 stages x A,B)
#define G_SMEM_B  (G_PIPE_B)                    // epilogue C tile 67584 fits

__device__ __forceinline__ void gemm_mainloop(
    const __half* __restrict__ A, const __half* __restrict__ Bt,
    int mBase, int nBase, int K, uint32_t smb,
    int tid, int lane, int wm, int wn, float acc[2][8][4])
{
    const int NC = K >> 5;                      // 32-wide chunks
    const int lrow = tid >> 1;
    const int lseg = (tid & 1) << 4;
    const int ldRow = lane & 15;
    const int ldCol = (lane >> 4) << 3;

    const __half* gA = A  + (size_t)(mBase + lrow) * K + lseg;
    const __half* gB = Bt + (size_t)(nBase + lrow) * K + lseg;
    const uint32_t sOff = (uint32_t)(lrow * GST + lseg) * 2;

    auto issue = [&](int c, int s) {
        const __half* ga = gA + c * 32;
        const __half* gb = gB + c * 32;
        uint32_t sa = smb + (uint32_t)s * (GSTAGE_H * 2) + sOff;
        uint32_t sb = smb + (uint32_t)(4 * GSTAGE_H * 2) + (uint32_t)s * (GSTAGE_H * 2) + sOff;
        cp_async16(sa,      ga);
        cp_async16(sa + 16, ga + 8);
        cp_async16(sb,      gb);
        cp_async16(sb + 16, gb + 8);
        CP_COMMIT();
    };

    issue(0, 0);
    issue(1, 1);
    issue(2, 2);

    int stage = 0;
    for (int c = 0; c < NC; ++c) {
        int rem = NC - 1 - c;                    // chunks after this one
        if (rem >= 2)      CP_WAIT2();
        else if (rem == 1) CP_WAIT1();
        else               CP_WAIT0();
        __syncthreads();
        if (c + 3 < NC) {
            int ns = stage + 3; if (ns >= 4) ns -= 4;
            issue(c + 3, ns);
        }
        const uint32_t sA = smb + (uint32_t)stage * (GSTAGE_H * 2);
        const uint32_t sB = smb + (uint32_t)(4 * GSTAGE_H * 2) + (uint32_t)stage * (GSTAGE_H * 2);
        #pragma unroll
        for (int ks = 0; ks < 2; ++ks) {
            uint32_t af[2][4], bfr[8][2];
            #pragma unroll
            for (int mf = 0; mf < 2; ++mf) {
                uint32_t addr = sA + ((wm * 32 + mf * 16 + ldRow) * GST
                                      + ks * 16 + ldCol) * 2;
                ldm_x4(af[mf][0], af[mf][1], af[mf][2], af[mf][3], addr);
            }
            #pragma unroll
            for (int ng = 0; ng < 4; ++ng) {
                uint32_t r0, r1, r2, r3;
                uint32_t addr = sB + ((wn * 64 + ng * 16 + ldRow) * GST
                                      + ks * 16 + ldCol) * 2;
                ldm_x4(r0, r1, r2, r3, addr);
                bfr[ng * 2 + 0][0] = r0; bfr[ng * 2 + 1][0] = r1;
                bfr[ng * 2 + 0][1] = r2; bfr[ng * 2 + 1][1] = r3;
            }
            #pragma unroll
            for (int mf = 0; mf < 2; ++mf)
                #pragma unroll
                for (int nf = 0; nf < 8; ++nf)
                    mma16816(acc[mf][nf], af[mf], bfr[nf]);
        }
        ++stage; if (stage == 4) stage = 0;
    }
}

// ---------------- GEMM with plain fp32 epilogue (output projection) ----------
__global__ __launch_bounds__(256, 2) void gemm_kernel(
    const __half* __restrict__ A, const __half* __restrict__ Bt,
    float* __restrict__ C, int N, int K)
{
    extern __shared__ __half gsm[];
    const uint32_t smb = smem_u32(gsm);
    const int tid = threadIdx.x;
    const int lane = tid & 31, wid = tid >> 5;
    const int wm = wid & 3, wn = wid >> 2;
    const int mBase = blockIdx.y << 7, nBase = blockIdx.x << 7;

    float acc[2][8][4];
    #pragma unroll
    for (int i = 0; i < 2; ++i)
        #pragma unroll
        for (int j = 0; j < 8; ++j)
            #pragma unroll
            for (int r = 0; r < 4; ++r) acc[i][j][r] = 0.f;

    gemm_mainloop(A, Bt, mBase, nBase, K, smb, tid, lane, wm, wn, acc);

    const int gid = lane >> 2, tig = lane & 3;
    #pragma unroll
    for (int mf = 0; mf < 2; ++mf) {
        #pragma unroll
        for (int nf = 0; nf < 8; ++nf) {
            int row = mBase + wm * 32 + mf * 16 + gid;
            int col = nBase + wn * 64 + nf * 8 + tig * 2;
            float2 v0 = make_float2(acc[mf][nf][0], acc[mf][nf][1]);
            float2 v1 = make_float2(acc[mf][nf][2], acc[mf][nf][3]);
            *(float2*)&C[(size_t)row * N + col] = v0;
            *(float2*)&C[(size_t)(row + 8) * N + col] = v1;
        }
    }
}

// ---------------- fused QKV GEMM: rope + fp16 convert in epilogue ------------
__global__ __launch_bounds__(256, 2) void gemm_qkv_kernel(
    const __half* __restrict__ A, const __half* __restrict__ Bt,
    __half* __restrict__ qf, __half* __restrict__ kf, __half* __restrict__ vf,
    int K)
{
    extern __shared__ __half gsm[];
    const uint32_t smb = smem_u32(gsm);
    const int tid = threadIdx.x;
    const int lane = tid & 31, wid = tid >> 5;
    const int wm = wid & 3, wn = wid >> 2;
    const int mBase = blockIdx.y << 7, nBase = blockIdx.x << 7;

    float acc[2][8][4];
    #pragma unroll
    for (int i = 0; i < 2; ++i)
        #pragma unroll
        for (int j = 0; j < 8; ++j)
            #pragma unroll
            for (int r = 0; r < 4; ++r) acc[i][j][r] = 0.f;

    gemm_mainloop(A, Bt, mBase, nBase, K, smb, tid, lane, wm, wn, acc);

    // stage fp32 C tile in smem (reuse pipeline buffers)
    float* Cs = (float*)gsm;
    __syncthreads();
    const int gid = lane >> 2, tig = lane & 3;
    #pragma unroll
    for (int mf = 0; mf < 2; ++mf) {
        #pragma unroll
        for (int nf = 0; nf < 8; ++nf) {
            int r = wm * 32 + mf * 16 + gid;
            int col = wn * 64 + nf * 8 + tig * 2;
            *(float2*)&Cs[r * 132 + col] = make_float2(acc[mf][nf][0], acc[mf][nf][1]);
            *(float2*)&Cs[(r + 8) * 132 + col] = make_float2(acc[mf][nf][2], acc[mf][nf][3]);
        }
    }
    __syncthreads();

    if (nBase < 2048) {                    // Q head: rope + scale
        for (int p = tid; p < 128 * 64; p += 256) {
            int r = p >> 6, d = p & 63;
            int row = mBase + r;
            int t = row & (TT - 1);
            float c = g_rcos[t * 64 + d], s = g_rsin[t * 64 + d];
            float u1 = Cs[r * 132 + d], u2 = Cs[r * 132 + d + 64];
            __half* op = qf + (size_t)row * 2048 + nBase;
            op[d]      = __float2half((u1 * c - u2 * s) * QSCALE);
            op[d + 64] = __float2half((u2 * c + u1 * s) * QSCALE);
        }
    } else if (nBase < 2560) {             // K head: rope
        int colb = nBase - 2048;
        for (int p = tid; p < 128 * 64; p += 256) {
            int r = p >> 6, d = p & 63;
            int row = mBase + r;
            int t = row & (TT - 1);
            float c = g_rcos[t * 64 + d], s = g_rsin[t * 64 + d];
            float u1 = Cs[r * 132 + d], u2 = Cs[r * 132 + d + 64];
            __half* op = kf + (size_t)row * 512 + colb;
            op[d]      = __float2half(u1 * c - u2 * s);
            op[d + 64] = __float2half(u2 * c + u1 * s);
        }
    } else {                               // V: plain convert
        int colb = nBase - 2560;
        for (int p = tid; p < 128 * 128; p += 256) {
            int r = p >> 7, d = p & 127;
            int row = mBase + r;
            vf[(size_t)row * 512 + colb + d] = __float2half(Cs[r * 132 + d]);
        }
    }
}

// ---------------- fp16 tensor-core flash attention (2-stage K/V pipeline) ----
#define AST 136
#define ATT_SMEM (5 * 64 * AST * 2)   // Q + 2 x (K,V) stages = 87040 B

__global__ __launch_bounds__(128) void attn_mma_kernel(
    const __half* __restrict__ Qf, const __half* __restrict__ Kf,
    const __half* __restrict__ Vf, __half* __restrict__ Oo)
{
    extern __shared__ __half smh[];
    __half* sQ = smh;
    __half* sKV = sQ + 64 * AST;

    const int tid = threadIdx.x;
    const int lane = tid & 31, wm = tid >> 5;
    const int gid = lane >> 2, tig = lane & 3;
    const int ldRow = lane & 15, ldCol = (lane >> 4) << 3;
    const int qt = gridDim.x - 1 - blockIdx.x;
    const int h = blockIdx.y, b = blockIdx.z;
    const int hk = h >> 2;
    const int qBase = qt * 64;

    const uint32_t aQ = smem_u32(sQ);
    const uint32_t aKV = smem_u32(sKV);
    const uint32_t stageB = 2 * 64 * AST * 2;
    const uint32_t vOffB  = 64 * AST * 2;

    auto issue = [&](int kt, int s) {
        const size_t base = ((size_t)(b * TT + kt * 64)) * 512 + hk * 128;
        uint32_t sk = aKV + (uint32_t)s * stageB;
        #pragma unroll
        for (int j = 0; j < 8; ++j) {
            int idx = j * 128 + tid;
            int r = idx >> 4, c = (idx & 15) << 3;
            size_t g = base + (size_t)r * 512 + c;
            uint32_t so = (uint32_t)(r * AST + c) * 2;
            cp_async16(sk + so, Kf + g);
            cp_async16(sk + vOffB + so, Vf + g);
        }
        CP_COMMIT();
    };

    issue(0, 0);

    {
        const __half* gq = Qf + ((size_t)(b * TT + qBase)) * 2048 + h * 128;
        for (int idx = tid; idx < 1024; idx += 128) {
            int r = idx >> 4, c = (idx & 15) << 3;
            *(uint4*)&sQ[r * AST + c] = *(const uint4*)(gq + (size_t)r * 2048 + c);
        }
    }

    float oacc[16][4];
    #pragma unroll
    for (int i = 0; i < 16; ++i)
        #pragma unroll
        for (int r = 0; r < 4; ++r) oacc[i][r] = 0.f;
    float mrow[2] = {-INFINITY, -INFINITY};
    float lrow[2] = {0.f, 0.f};

    for (int kt = 0; kt <= qt; ++kt) {
        __syncthreads();
        if (kt + 1 <= qt) { issue(kt + 1, (kt + 1) & 1); CP_WAIT1(); }
        else              { CP_WAIT0(); }
        __syncthreads();

        const uint32_t aK = aKV + (uint32_t)(kt & 1) * stageB;
        const uint32_t aV = aK + vOffB;

        float sacc[8][4];
        #pragma unroll
        for (int i = 0; i < 8; ++i)
            #pragma unroll
            for (int r = 0; r < 4; ++r) sacc[i][r] = 0.f;

        #pragma unroll
        for (int ks = 0; ks < 8; ++ks) {
            uint32_t aq[4];
            uint32_t qoff = ((wm * 16 + ldRow) * AST + ks * 16 + ldCol) * 2;
            ldm_x4(aq[0], aq[1], aq[2], aq[3], aQ + qoff);
            #pragma unroll
            for (int j = 0; j < 4; ++j) {
                uint32_t koff = ((j * 16 + ldRow) * AST + ks * 16 + ldCol) * 2;
                uint32_t r0, r1, r2, r3;
                ldm_x4(r0, r1, r2, r3, aK + koff);
                uint32_t b0[2] = {r0, r2}, b1[2] = {r1, r3};
                mma16816(sacc[2 * j], aq, b0);
                mma16816(sacc[2 * j + 1], aq, b1);
            }
        }

        if (kt == qt) {
            int lr0 = wm * 16 + gid, lr1 = lr0 + 8;
            #pragma unroll
            for (int nb = 0; nb < 8; ++nb) {
                int lc = nb * 8 + tig * 2;
                if (lc > lr0)     sacc[nb][0] = -1e30f;
                if (lc + 1 > lr0) sacc[nb][1] = -1e30f;
                if (lc > lr1)     sacc[nb][2] = -1e30f;
                if (lc + 1 > lr1) sacc[nb][3] = -1e30f;
            }
        }

        #pragma unroll
        for (int hf = 0; hf < 2; ++hf) {
            float rmax = -1e30f;
            #pragma unroll
            for (int nb = 0; nb < 8; ++nb)
                rmax = fmaxf(rmax, fmaxf(sacc[nb][hf * 2], sacc[nb][hf * 2 + 1]));
            rmax = fmaxf(rmax, __shfl_xor_sync(0xffffffffu, rmax, 1));
            rmax = fmaxf(rmax, __shfl_xor_sync(0xffffffffu, rmax, 2));
            float mnew = fmaxf(mrow[hf], rmax);
            float f = __expf(mrow[hf] - mnew);
            mrow[hf] = mnew;
            float rsum = 0.f;
            #pragma unroll
            for (int nb = 0; nb < 8; ++nb) {
                float s0 = __expf(sacc[nb][hf * 2] - mnew);
                float s1 = __expf(sacc[nb][hf * 2 + 1] - mnew);
                sacc[nb][hf * 2] = s0;
                sacc[nb][hf * 2 + 1] = s1;
                rsum += s0 + s1;
            }
            rsum += __shfl_xor_sync(0xffffffffu, rsum, 1);
            rsum += __shfl_xor_sync(0xffffffffu, rsum, 2);
            lrow[hf] = lrow[hf] * f + rsum;
            #pragma unroll
            for (int nb = 0; nb < 16; ++nb) {
                oacc[nb][hf * 2] *= f;
                oacc[nb][hf * 2 + 1] *= f;
            }
        }

        uint32_t ph[4][4];
        #pragma unroll
        for (int ks = 0; ks < 4; ++ks) {
            ph[ks][0] = pack_h2(sacc[2 * ks][0], sacc[2 * ks][1]);
            ph[ks][1] = pack_h2(sacc[2 * ks][2], sacc[2 * ks][3]);
            ph[ks][2] = pack_h2(sacc[2 * ks + 1][0], sacc[2 * ks + 1][1]);
            ph[ks][3] = pack_h2(sacc[2 * ks + 1][2], sacc[2 * ks + 1][3]);
        }

        #pragma unroll
        for (int ks = 0; ks < 4; ++ks) {
            #pragma unroll
            for (int j = 0; j < 8; ++j) {
                uint32_t voff = ((ks * 16 + ldRow) * AST + j * 16 + ldCol) * 2;
                uint32_t r0, r1, r2, r3;
                ldm_x4t(r0, r1, r2, r3, aV + voff);
                uint32_t v0[2] = {r0, r1}, v1[2] = {r2, r3};
                mma16816(oacc[2 * j], ph[ks], v0);
                mma16816(oacc[2 * j + 1], ph[ks], v1);
            }
        }
    }

    float inv0 = 1.f / lrow[0], inv1 = 1.f / lrow[1];
    size_t row0 = (size_t)(b * TT + qBase + wm * 16 + gid);
    __half* p0 = Oo + row0 * KDIM + h * 128 + tig * 2;
    __half* p1 = Oo + (row0 + 8) * KDIM + h * 128 + tig * 2;
    #pragma unroll
    for (int nb = 0; nb < 16; ++nb) {
        *(uint32_t*)(p0 + nb * 8) = pack_h2(oacc[nb][0] * inv0, oacc[nb][1] * inv0);
        *(uint32_t*)(p1 + nb * 8) = pack_h2(oacc[nb][2] * inv1, oacc[nb][3] * inv1);
    }
}

// ---------------- launcher ---------------------------------------------------
extern "C" void kernel_launch(void* const* d_in, const int* in_sizes, int n_in,
                              void* d_out, int out_size)
{
    const float* x  = (const float*)d_in[0];
    const float* wq = (const float*)d_in[1];
    const float* wk = (const float*)d_in[2];
    const float* wv = (const float*)d_in[3];
    const float* wo = (const float*)d_in[4];
    float* out = (float*)d_out;

    __half *xh, *ah, *wqkvt, *wot, *qf, *kf, *vf;
    cudaGetSymbolAddress((void**)&xh, g_xh);
    cudaGetSymbolAddress((void**)&ah, g_ah);
    cudaGetSymbolAddress((void**)&wqkvt, g_wqkvt);
    cudaGetSymbolAddress((void**)&wot, g_wot);
    cudaGetSymbolAddress((void**)&qf, g_Qf);
    cudaGetSymbolAddress((void**)&kf, g_Kf);
    cudaGetSymbolAddress((void**)&vf, g_Vf);

    cudaFuncSetAttribute(attn_mma_kernel,
                         cudaFuncAttributeMaxDynamicSharedMemorySize, ATT_SMEM);
    cudaFuncSetAttribute(gemm_kernel,
                         cudaFuncAttributeMaxDynamicSharedMemorySize, G_SMEM_B);
    cudaFuncSetAttribute(gemm_qkv_kernel,
                         cudaFuncAttributeMaxDynamicSharedMemorySize, G_SMEM_B);

    // all conversions + rope table in ONE launch
    megaconv_kernel<<<MEGACONV_BLOCKS, 256>>>(x, wq, wk, wv, wo, xh, wqkvt, wot);

    // fused QKV projection + rope + fp16 convert (one GEMM, N=3072)
    gemm_qkv_kernel<<<dim3(NQKV / 128, BT / 128), 256, G_SMEM_B>>>(xh, wqkvt,
                                                                   qf, kf, vf, KDIM);

    // fp16 tensor-core flash attention -> ah
    attn_mma_kernel<<<dim3(TT / 64, NH, BB), 128, ATT_SMEM>>>(qf, kf, vf, ah);

    // Output projection (fp32 out)
    gemm_kernel<<<dim3(2048 / 128, BT / 128), 256, G_SMEM_B>>>(ah, wot, out, 2048, KDIM);
}